// round 1
// baseline (speedup 1.0000x reference)
#include <cuda_runtime.h>

#define Bc 32
#define Lc 128
#define Hc 100
#define Pc 20
#define HPAD 101
#define HPAD4 104
#define NCOL 105
#define EPSF 1e-8f
#define MINV -1e7f

// ---------------- scratch (device globals; no allocation allowed) ----------------
__device__ float g_v[2*Bc*Lc*Hc];        // masked vectors, [side][b][i][h]
__device__ float g_norm[2*Bc*Lc];
__device__ float g_maskf[2*Bc*Lc];
__device__ float g_nw[2*Bc*Lc*Pc];       // ||w1[p]*v_i|| per token
__device__ float g_cnt[2*Bc];
__device__ float g_maxm[2*Bc];
__device__ float g_last[2*Bc*Hc];
__device__ float g_cos[Bc*Lc*Lc];
__device__ float g_cmax[2*Bc*Lc];        // raw masked max (init MINV)
__device__ float g_cmsum[2*Bc*Lc];       // masked sum
__device__ float g_cfsum[2*Bc*Lc];       // full (unmasked) sum
__device__ float g_attmean[2*Bc*Lc*Hc];
__device__ float g_attmax[2*Bc*Lc*Hc];
__device__ float g_mvmax[2*Bc*Lc*Pc];
__device__ float g_mvmean[2*Bc*Lc*Pc];

// ---------------- f32x2 packed math helpers ----------------
__device__ __forceinline__ void fma2(unsigned long long &acc, unsigned long long a, unsigned long long b){
    asm("fma.rn.f32x2 %0, %1, %2, %0;" : "+l"(acc) : "l"(a), "l"(b));
}
__device__ __forceinline__ unsigned long long pack2f(float lo, float hi){
    unsigned long long r; asm("mov.b64 %0, {%1,%2};" : "=l"(r) : "f"(lo), "f"(hi)); return r;
}
__device__ __forceinline__ unsigned long long add2(unsigned long long a, unsigned long long b){
    unsigned long long r; asm("add.rn.f32x2 %0, %1, %2;" : "=l"(r) : "l"(a), "l"(b)); return r;
}
__device__ __forceinline__ float sum2f(unsigned long long v){
    float lo, hi; asm("mov.b64 {%0,%1}, %2;" : "=f"(lo), "=f"(hi) : "l"(v)); return lo + hi;
}

// ---------------- K0: mask, norms, weighted norms, counts, last token ----------------
__global__ void k0_prep(const float* __restrict__ ctxp, const int* __restrict__ maskp,
                        const float* __restrict__ ctxh, const int* __restrict__ maskh,
                        const float* __restrict__ w1) {
    int b = blockIdx.x, s = blockIdx.y;
    int i = threadIdx.x;   // token
    const float* ctx = (s == 0) ? ctxp : ctxh;
    const int*   mk  = (s == 0) ? maskp : maskh;
    int mi = mk[b*Lc + i];
    float m = (float)mi;

    float x[Hc];
    float ssq = 0.f;
    const float* src = ctx + (size_t)(b*Lc + i)*Hc;
    #pragma unroll
    for (int h = 0; h < Hc; h++) {
        float t = src[h] * m;
        x[h] = t; ssq += t*t;
        g_v[((s*Bc + b)*Lc + i)*Hc + h] = t;
    }
    g_norm[(s*Bc + b)*Lc + i]  = sqrtf(ssq);
    g_maskf[(s*Bc + b)*Lc + i] = m;

    for (int p = 0; p < Pc; p++) {
        float acc = 0.f;
        #pragma unroll
        for (int h = 0; h < Hc; h++) {
            float w = __ldg(&w1[p*Hc + h]);
            float t = w * x[h];
            acc += t*t;
        }
        g_nw[((s*Bc + b)*Lc + i)*Pc + p] = sqrtf(acc);
    }

    __shared__ int scnt, smax, sidx;
    if (i == 0) { scnt = 0; smax = 0; }
    __syncthreads();
    atomicAdd(&scnt, mi);
    atomicMax(&smax, mi);
    __syncthreads();
    if (i == 0) {
        g_cnt[s*Bc + b]  = (float)scnt;
        g_maxm[s*Bc + b] = (float)smax;
        sidx = (scnt > 0) ? scnt - 1 : 0;
    }
    __syncthreads();
    if (i < Hc) g_last[(s*Bc + b)*Hc + i] = g_v[((s*Bc + b)*Lc + sidx)*Hc + i];
}

// ---------------- K1: cos matrix + p-side row stats ----------------
// grid (B, 16), 256 threads: 8 rows per block, each row owned by one warp.
__global__ void k1_cos() {
    extern __shared__ float sm[];
    float* ch = sm;                  // 128*101
    float* mh = ch + Lc*HPAD;        // 128
    float* nh = mh + Lc;             // 128
    float* cp = nh + Lc;             // 8*101
    int b = blockIdx.x;
    int i0 = blockIdx.y * 8;
    int tid = threadIdx.x;

    for (int idx = tid; idx < Lc*Hc; idx += 256) {
        int j = idx / Hc, h = idx - j*Hc;
        ch[j*HPAD + h] = g_v[((1*Bc + b)*Lc + j)*Hc + h];
    }
    for (int idx = tid; idx < 8*Hc; idx += 256) {
        int il = idx / Hc, h = idx - il*Hc;
        cp[il*HPAD + h] = g_v[((0*Bc + b)*Lc + i0 + il)*Hc + h];
    }
    if (tid < Lc) {
        mh[tid] = g_maskf[(1*Bc + b)*Lc + tid];
        nh[tid] = g_norm[(1*Bc + b)*Lc + tid];
    }
    __syncthreads();

    int g = tid >> 5, lane = tid & 31;
    int i = i0 + g;
    float ni = g_norm[(0*Bc + b)*Lc + i];
    float vmax = MINV, msum = 0.f, fsum = 0.f;

    for (int jj = 0; jj < 4; jj++) {
        int j = jj*32 + lane;
        float a0=0.f, a1=0.f, a2=0.f, a3=0.f;
        #pragma unroll
        for (int h = 0; h < Hc; h += 4) {
            a0 += cp[g*HPAD + h+0] * ch[j*HPAD + h+0];
            a1 += cp[g*HPAD + h+1] * ch[j*HPAD + h+1];
            a2 += cp[g*HPAD + h+2] * ch[j*HPAD + h+2];
            a3 += cp[g*HPAD + h+3] * ch[j*HPAD + h+3];
        }
        float dot = (a0+a1)+(a2+a3);
        float c = __fdividef(dot, fmaxf(ni*nh[j], EPSF));
        g_cos[(b*Lc + i)*Lc + j] = c;
        fsum += c;
        if (mh[j] > 0.f) { vmax = fmaxf(vmax, c); msum += c; }
    }
    #pragma unroll
    for (int o = 16; o; o >>= 1) {
        vmax = fmaxf(vmax, __shfl_xor_sync(0xffffffffu, vmax, o));
        msum += __shfl_xor_sync(0xffffffffu, msum, o);
        fsum += __shfl_xor_sync(0xffffffffu, fsum, o);
    }
    if (lane == 0) {
        g_cmax[(0*Bc + b)*Lc + i]  = vmax;
        g_cmsum[(0*Bc + b)*Lc + i] = msum;
        g_cfsum[(0*Bc + b)*Lc + i] = fsum;
    }
}

// ---------------- K2: h-side column stats of cos ----------------
__global__ void k2_colstats() {
    int b = blockIdx.x, j = threadIdx.x;
    __shared__ float mp[Lc];
    mp[j] = g_maskf[(0*Bc + b)*Lc + j];
    __syncthreads();
    float vmax = MINV, msum = 0.f, fsum = 0.f;
    for (int i = 0; i < Lc; i++) {
        float v = g_cos[(b*Lc + i)*Lc + j];
        fsum += v;
        if (mp[i] > 0.f) { vmax = fmaxf(vmax, v); msum += v; }
    }
    g_cmax[(1*Bc + b)*Lc + j]  = vmax;
    g_cmsum[(1*Bc + b)*Lc + j] = msum;
    g_cfsum[(1*Bc + b)*Lc + j] = fsum;
}

// ---------------- K3: attentive mean + max-attentive vectors ----------------
// grid (B, 32, 2): 4 output rows per block; thread = h lane.
__global__ void k3_att() {
    int b = blockIdx.x, r0 = blockIdx.y * 4, s = blockIdx.z, o = 1 - s;
    int tid = threadIdx.x; // 128
    __shared__ float coef[4][Lc];
    __shared__ float m2s[Lc];

    if (s == 0) {
        #pragma unroll
        for (int rl = 0; rl < 4; rl++) coef[rl][tid] = g_cos[(b*Lc + r0 + rl)*Lc + tid];
    } else {
        float4 v4 = *(const float4*)&g_cos[(b*Lc + tid)*Lc + r0];
        coef[0][tid] = v4.x; coef[1][tid] = v4.y; coef[2][tid] = v4.z; coef[3][tid] = v4.w;
    }
    m2s[tid] = g_maskf[(o*Bc + b)*Lc + tid];
    __syncthreads();

    if (tid < Hc) {
        float acc[4] = {0.f,0.f,0.f,0.f};
        float axv[4] = {MINV,MINV,MINV,MINV};
        for (int k = 0; k < Lc; k++) {
            float pv = g_v[((o*Bc + b)*Lc + k)*Hc + tid];
            float mm = m2s[k];
            #pragma unroll
            for (int rl = 0; rl < 4; rl++) {
                float prod = coef[rl][k] * pv;
                acc[rl] += prod;
                if (mm > 0.f) axv[rl] = fmaxf(axv[rl], prod);
            }
        }
        float maxm2 = g_maxm[o*Bc + b];
        #pragma unroll
        for (int rl = 0; rl < 4; rl++) {
            int r = r0 + rl;
            float fs   = g_cfsum[(s*Bc + b)*Lc + r];
            float mfac = g_maskf[(s*Bc + b)*Lc + r] * maxm2;
            g_attmean[((s*Bc + b)*Lc + r)*Hc + tid] = __fdividef(acc[rl], fmaxf(fs, EPSF));
            g_attmax [((s*Bc + b)*Lc + r)*Hc + tid] = axv[rl] * mfac;
        }
    }
}

// ---------------- K4: heavy pairwise multi-perspective (w1) ----------------
// grid (B, 8, 2); 320 threads = 16 i x 20 p. f32x2 packed FMA inner loop.
__global__ __launch_bounds__(320, 1) void k4_pairwise(const float* __restrict__ w1) {
    extern __shared__ float sm[];
    float* ch  = sm;                    // 128*104 (16B-aligned rows)
    float* nw2 = ch + Lc*HPAD4;         // 128*20
    float* m2  = nw2 + Lc*Pc;           // 128
    float* v1t = m2 + Lc;               // 16*101
    int b = blockIdx.x, it = blockIdx.y, s = blockIdx.z, o = 1 - s;
    int tid = threadIdx.x;
    int i0 = it * 16;

    for (int idx = tid; idx < Lc*Hc; idx += 320) {
        int j = idx / Hc, h = idx - j*Hc;
        ch[j*HPAD4 + h] = g_v[((o*Bc + b)*Lc + j)*Hc + h];
    }
    for (int idx = tid; idx < Lc*Pc; idx += 320)
        nw2[idx] = g_nw[((o*Bc + b)*Lc)*Pc + idx];
    if (tid < Lc) m2[tid] = g_maskf[(o*Bc + b)*Lc + tid];
    for (int idx = tid; idx < 16*Hc; idx += 320) {
        int il = idx / Hc, h = idx - il*Hc;
        v1t[il*HPAD + h] = g_v[((s*Bc + b)*Lc + i0 + il)*Hc + h];
    }
    __syncthreads();

    int il = tid / Pc, p = tid - il*Pc;
    int i = i0 + il;

    unsigned long long wcp[50];
    #pragma unroll
    for (int q = 0; q < 50; q++) {
        float wa = __ldg(&w1[p*Hc + 2*q]);
        float wb = __ldg(&w1[p*Hc + 2*q + 1]);
        wcp[q] = pack2f(wa*wa*v1t[il*HPAD + 2*q], wb*wb*v1t[il*HPAD + 2*q + 1]);
    }
    float nw1v = g_nw[((s*Bc + b)*Lc + i)*Pc + p];
    float m1   = g_maskf[(s*Bc + b)*Lc + i];

    float vmax = MINV, vsum = 0.f;
    for (int j = 0; j < Lc; j++) {
        const ulonglong2* row = (const ulonglong2*)&ch[j*HPAD4];
        unsigned long long a0 = 0ull, a1 = 0ull, a2 = 0ull, a3 = 0ull;
        #pragma unroll
        for (int q = 0; q < 25; q++) {
            ulonglong2 cc = row[q];   // 4 floats of ch[j]
            if (q & 1) { fma2(a2, wcp[2*q], cc.x); fma2(a3, wcp[2*q + 1], cc.y); }
            else       { fma2(a0, wcp[2*q], cc.x); fma2(a1, wcp[2*q + 1], cc.y); }
        }
        float dot = sum2f(add2(add2(a0, a1), add2(a2, a3)));
        float den = fmaxf(nw1v * nw2[j*Pc + p], EPSF);
        float val = __fdividef(dot, den);
        if (m2[j] > 0.f) { vmax = fmaxf(vmax, val); vsum += val; }
    }
    float m = m1 * g_maxm[o*Bc + b];
    g_mvmax [((s*Bc + b)*Lc + i)*Pc + p] = vmax * m;
    g_mvmean[((s*Bc + b)*Lc + i)*Pc + p] = (m1 * vsum) / fmaxf(m1 * g_cnt[o*Bc + b], EPSF);
}

// ---------------- K5: final cos-sims + assembly of 105 columns ----------------
// grid (B, 2, 8); 336 threads = 16 i x 21 slots (slot 0 = unweighted, 1..20 = p).
__global__ __launch_bounds__(336) void k5_final(const float* __restrict__ w0,
                                                const float* __restrict__ w2,
                                                const float* __restrict__ w3,
                                                float* __restrict__ out) {
    int b = blockIdx.x, s = blockIdx.y, it = blockIdx.z, o = 1 - s;
    int i0 = it * 16;
    int tid = threadIdx.x;

    __shared__ float v1t[16][HPAD];
    __shared__ float amn[16][HPAD];
    __shared__ float amx[16][HPAD];
    __shared__ float lastv[Hc];
    __shared__ float wsq[3][Hc][Pc];

    for (int idx = tid; idx < 16*Hc; idx += 336) {
        int il = idx / Hc, h = idx - il*Hc;
        int base = ((s*Bc + b)*Lc + i0 + il)*Hc + h;
        v1t[il][h] = g_v[base];
        amn[il][h] = g_attmean[base];
        amx[il][h] = g_attmax[base];
    }
    for (int idx = tid; idx < Hc; idx += 336) lastv[idx] = g_last[(o*Bc + b)*Hc + idx];
    for (int idx = tid; idx < 3*Hc*Pc; idx += 336) {
        int pr = idx / (Hc*Pc);
        int r2 = idx - pr*(Hc*Pc);
        int h = r2 / Pc, p = r2 - h*Pc;
        const float* w = (pr == 0) ? w0 : ((pr == 1) ? w2 : w3);
        float wv = w[p*Hc + h];
        wsq[pr][h][p] = wv*wv;
    }
    __syncthreads();

    int il = tid / 21, q = tid - il*21;
    int i = i0 + il;
    float m1    = g_maskf[(s*Bc + b)*Lc + i];
    float cnt2  = g_cnt[o*Bc + b];
    float maxm2 = g_maxm[o*Bc + b];
    float* orow = out + (size_t)s*(Bc*Lc*NCOL) + (size_t)(b*Lc + i)*NCOL;

    if (q == 0) {
        orow[0] = g_cmax[(s*Bc + b)*Lc + i] * (m1 * maxm2);
        orow[1] = (m1 * g_cmsum[(s*Bc + b)*Lc + i]) / fmaxf(m1 * cnt2, EPSF);
    } else {
        int p = q - 1;
        orow[23 + p] = g_mvmax [((s*Bc + b)*Lc + i)*Pc + p];
        orow[43 + p] = g_mvmean[((s*Bc + b)*Lc + i)*Pc + p];
    }

    #pragma unroll
    for (int pr = 0; pr < 3; pr++) {
        const float* part = (pr == 0) ? lastv : ((pr == 1) ? &amn[il][0] : &amx[il][0]);
        float saa = 0.f, sab = 0.f, sbb = 0.f;
        if (q == 0) {
            #pragma unroll 4
            for (int h = 0; h < Hc; h++) {
                float a = v1t[il][h], bv = part[h];
                sab = fmaf(a, bv, sab);
                saa = fmaf(a, a, saa);
                sbb = fmaf(bv, bv, sbb);
            }
        } else {
            int p = q - 1;
            #pragma unroll 4
            for (int h = 0; h < Hc; h++) {
                float a = v1t[il][h], bv = part[h], w = wsq[pr][h][p];
                sab = fmaf(w, a*bv, sab);
                saa = fmaf(w, a*a, saa);
                sbb = fmaf(w, bv*bv, sbb);
            }
        }
        float val = sab / (fmaxf(sqrtf(saa), EPSF) * fmaxf(sqrtf(sbb), EPSF));
        int col = (pr == 0) ? ((q == 0) ? 2 : 3 + (q - 1))
                : (pr == 1) ? ((q == 0) ? 63 : 64 + (q - 1))
                :             ((q == 0) ? 84 : 85 + (q - 1));
        orow[col] = val;
    }
}

// ---------------- launch ----------------
extern "C" void kernel_launch(void* const* d_in, const int* in_sizes, int n_in,
                              void* d_out, int out_size) {
    const float* ctxp  = (const float*)d_in[0];
    const int*   maskp = (const int*)  d_in[1];
    const float* ctxh  = (const float*)d_in[2];
    const int*   maskh = (const int*)  d_in[3];
    const float* w0    = (const float*)d_in[4];
    const float* w1    = (const float*)d_in[5];
    const float* w2    = (const float*)d_in[6];
    const float* w3    = (const float*)d_in[7];
    float* out = (float*)d_out;

    const int SM1 = (Lc*HPAD + Lc + Lc + 8*HPAD) * 4;            // 55968 B
    const int SM4 = (Lc*HPAD4 + Lc*Pc + Lc + 16*HPAD) * 4;       // 70464 B
    cudaFuncSetAttribute(k1_cos,      cudaFuncAttributeMaxDynamicSharedMemorySize, SM1);
    cudaFuncSetAttribute(k4_pairwise, cudaFuncAttributeMaxDynamicSharedMemorySize, SM4);

    k0_prep<<<dim3(Bc, 2), Lc>>>(ctxp, maskp, ctxh, maskh, w1);
    k1_cos<<<dim3(Bc, 16), 256, SM1>>>();
    k2_colstats<<<Bc, Lc>>>();
    k3_att<<<dim3(Bc, Lc/4, 2), Lc>>>();
    k4_pairwise<<<dim3(Bc, 8, 2), 320, SM4>>>(w1);
    k5_final<<<dim3(Bc, 2, 8), 336>>>(w0, w2, w3, out);
}

// round 2
// speedup vs baseline: 1.0730x; 1.0730x over previous
#include <cuda_runtime.h>

#define Bc 32
#define Lc 128
#define Hc 100
#define Pc 20
#define HPAD 101
#define HPAD4 104
#define NCOL 105
#define EPSF 1e-8f
#define MINV -1e7f

// ---------------- scratch (device globals; no allocation allowed) ----------------
__device__ float g_v[2*Bc*Lc*Hc];        // masked vectors, [side][b][i][h]
__device__ float g_rnorm[2*Bc*Lc];       // 1/max(norm, eps)
__device__ float g_maskf[2*Bc*Lc];
__device__ float g_rnw[2*Bc*Lc*Pc];      // 1/max(||w1[p]*v_i||, eps)
__device__ float g_cnt[2*Bc];
__device__ float g_maxm[2*Bc];
__device__ float g_last[2*Bc*Hc];
__device__ float g_cos[Bc*Lc*Lc];        // [b][i][j]
__device__ float g_cosT[Bc*Lc*Lc];       // [b][j][i]
__device__ float g_cmax[2*Bc*Lc];        // raw masked max
__device__ float g_cmsum[2*Bc*Lc];       // masked sum
__device__ float g_cfsum[2*Bc*Lc];       // full (unmasked) sum
__device__ float g_attmean[2*Bc*Lc*Hc];
__device__ float g_attmax[2*Bc*Lc*Hc];

// ---------------- f32x2 packed math helpers ----------------
__device__ __forceinline__ void fma2(unsigned long long &acc, unsigned long long a, unsigned long long b){
    asm("fma.rn.f32x2 %0, %1, %2, %0;" : "+l"(acc) : "l"(a), "l"(b));
}
__device__ __forceinline__ unsigned long long pack2f(float lo, float hi){
    unsigned long long r; asm("mov.b64 %0, {%1,%2};" : "=l"(r) : "f"(lo), "f"(hi)); return r;
}
__device__ __forceinline__ unsigned long long add2(unsigned long long a, unsigned long long b){
    unsigned long long r; asm("add.rn.f32x2 %0, %1, %2;" : "=l"(r) : "l"(a), "l"(b)); return r;
}
__device__ __forceinline__ float sum2f(unsigned long long v){
    float lo, hi; asm("mov.b64 {%0,%1}, %2;" : "=f"(lo), "=f"(hi) : "l"(v)); return lo + hi;
}

// ---------------- K0: mask, reciprocal norms, weighted norms, counts, last token ----------------
__global__ void k0_prep(const float* __restrict__ ctxp, const int* __restrict__ maskp,
                        const float* __restrict__ ctxh, const int* __restrict__ maskh,
                        const float* __restrict__ w1) {
    int b = blockIdx.x, s = blockIdx.y;
    int i = threadIdx.x;   // token
    const float* ctx = (s == 0) ? ctxp : ctxh;
    const int*   mk  = (s == 0) ? maskp : maskh;
    int mi = mk[b*Lc + i];
    float m = (float)mi;

    float x[Hc];
    float ssq = 0.f;
    const float* src = ctx + (size_t)(b*Lc + i)*Hc;
    #pragma unroll
    for (int h = 0; h < Hc; h++) {
        float t = src[h] * m;
        x[h] = t; ssq += t*t;
        g_v[((s*Bc + b)*Lc + i)*Hc + h] = t;
    }
    g_rnorm[(s*Bc + b)*Lc + i] = 1.0f / fmaxf(sqrtf(ssq), EPSF);
    g_maskf[(s*Bc + b)*Lc + i] = m;

    for (int p = 0; p < Pc; p++) {
        float acc = 0.f;
        #pragma unroll
        for (int h = 0; h < Hc; h++) {
            float w = __ldg(&w1[p*Hc + h]);
            float t = w * x[h];
            acc += t*t;
        }
        g_rnw[((s*Bc + b)*Lc + i)*Pc + p] = 1.0f / fmaxf(sqrtf(acc), EPSF);
    }

    __shared__ int scnt, smax, sidx;
    if (i == 0) { scnt = 0; smax = 0; }
    __syncthreads();
    atomicAdd(&scnt, mi);
    atomicMax(&smax, mi);
    __syncthreads();
    if (i == 0) {
        g_cnt[s*Bc + b]  = (float)scnt;
        g_maxm[s*Bc + b] = (float)smax;
        sidx = (scnt > 0) ? scnt - 1 : 0;
    }
    __syncthreads();
    if (i < Hc) g_last[(s*Bc + b)*Hc + i] = g_v[((s*Bc + b)*Lc + sidx)*Hc + i];
}

// ---------------- K1: cos matrix (+transpose) + p-side row stats ----------------
// grid (B, 16), 256 threads: 8 rows per block, each row owned by one warp.
__global__ void k1_cos() {
    extern __shared__ float sm[];
    float* ch   = sm;                  // 128*101
    float* rnh  = ch + Lc*HPAD;        // 128
    float* mh   = rnh + Lc;            // 128
    float* negj = mh + Lc;             // 128
    float* cp   = negj + Lc;           // 8*101
    float* cs   = cp + 8*HPAD;         // 128*9 (transpose staging)
    int b = blockIdx.x;
    int i0 = blockIdx.y * 8;
    int tid = threadIdx.x;

    for (int idx = tid; idx < Lc*Hc; idx += 256) {
        int j = idx / Hc, h = idx - j*Hc;
        ch[j*HPAD + h] = g_v[((1*Bc + b)*Lc + j)*Hc + h];
    }
    for (int idx = tid; idx < 8*Hc; idx += 256) {
        int il = idx / Hc, h = idx - il*Hc;
        cp[il*HPAD + h] = g_v[((0*Bc + b)*Lc + i0 + il)*Hc + h];
    }
    if (tid < Lc) {
        rnh[tid] = g_rnorm[(1*Bc + b)*Lc + tid];
        float m  = g_maskf[(1*Bc + b)*Lc + tid];
        mh[tid]  = m;
        negj[tid] = (m > 0.f) ? 0.f : MINV;
    }
    __syncthreads();

    int g = tid >> 5, lane = tid & 31;
    int i = i0 + g;
    float rni = g_rnorm[(0*Bc + b)*Lc + i];
    float vmax = MINV, msum = 0.f, fsum = 0.f;

    for (int jj = 0; jj < 4; jj++) {
        int j = jj*32 + lane;
        float a0=0.f, a1=0.f, a2=0.f, a3=0.f;
        #pragma unroll
        for (int h = 0; h < Hc; h += 4) {
            a0 += cp[g*HPAD + h+0] * ch[j*HPAD + h+0];
            a1 += cp[g*HPAD + h+1] * ch[j*HPAD + h+1];
            a2 += cp[g*HPAD + h+2] * ch[j*HPAD + h+2];
            a3 += cp[g*HPAD + h+3] * ch[j*HPAD + h+3];
        }
        float dot = (a0+a1)+(a2+a3);
        float c = dot * rni * rnh[j];
        g_cos[(b*Lc + i)*Lc + j] = c;
        cs[j*9 + g] = c;
        fsum += c;
        msum = fmaf(c, mh[j], msum);
        vmax = fmaxf(vmax, c + negj[j]);
    }
    #pragma unroll
    for (int o = 16; o; o >>= 1) {
        vmax = fmaxf(vmax, __shfl_xor_sync(0xffffffffu, vmax, o));
        msum += __shfl_xor_sync(0xffffffffu, msum, o);
        fsum += __shfl_xor_sync(0xffffffffu, fsum, o);
    }
    if (lane == 0) {
        g_cmax[(0*Bc + b)*Lc + i]  = vmax;
        g_cmsum[(0*Bc + b)*Lc + i] = msum;
        g_cfsum[(0*Bc + b)*Lc + i] = fsum;
    }
    __syncthreads();
    // transpose write: full 32B sectors per thread
    if (tid < Lc) {
        int j = tid;
        float4 v0, v1;
        v0.x = cs[j*9+0]; v0.y = cs[j*9+1]; v0.z = cs[j*9+2]; v0.w = cs[j*9+3];
        v1.x = cs[j*9+4]; v1.y = cs[j*9+5]; v1.z = cs[j*9+6]; v1.w = cs[j*9+7];
        float4* dst = reinterpret_cast<float4*>(&g_cosT[(b*Lc + j)*Lc + i0]);
        dst[0] = v0; dst[1] = v1;
    }
}

// ---------------- K2: h-side column stats of cos ----------------
__global__ void k2_colstats() {
    int b = blockIdx.x, j = threadIdx.x;
    __shared__ float mp[Lc], negp[Lc];
    float m = g_maskf[(0*Bc + b)*Lc + j];
    mp[j] = m;
    negp[j] = (m > 0.f) ? 0.f : MINV;
    __syncthreads();
    float vmax = MINV, msum = 0.f, fsum = 0.f;
    #pragma unroll 4
    for (int i = 0; i < Lc; i++) {
        float v = g_cos[(b*Lc + i)*Lc + j];
        fsum += v;
        msum = fmaf(v, mp[i], msum);
        vmax = fmaxf(vmax, v + negp[i]);
    }
    g_cmax[(1*Bc + b)*Lc + j]  = vmax;
    g_cmsum[(1*Bc + b)*Lc + j] = msum;
    g_cfsum[(1*Bc + b)*Lc + j] = fsum;
}

// ---------------- K3: attentive mean + max-attentive vectors ----------------
// grid (B, 16, 2): 8 output rows per block; thread = h lane. Branch-free mask.
__global__ void k3_att() {
    int b = blockIdx.x, r0 = blockIdx.y * 8, s = blockIdx.z, o = 1 - s;
    int tid = threadIdx.x; // 128
    __shared__ float coef[8][Lc];
    __shared__ float negk[Lc];

    const float* src = (s == 0) ? g_cos : g_cosT;  // cosT gives cos[:,k,r] rows
    #pragma unroll
    for (int rl = 0; rl < 8; rl++)
        coef[rl][tid] = src[(b*Lc + r0 + rl)*Lc + tid];
    negk[tid] = (g_maskf[(o*Bc + b)*Lc + tid] > 0.f) ? 0.f : MINV;
    __syncthreads();

    if (tid < Hc) {
        float acc[8], axv[8];
        #pragma unroll
        for (int rl = 0; rl < 8; rl++) { acc[rl] = 0.f; axv[rl] = MINV; }
        const float* vbase = &g_v[((size_t)(o*Bc + b)*Lc)*Hc + tid];
        for (int k = 0; k < Lc; k++) {
            float pv = __ldg(vbase + k*Hc);
            float nk = negk[k];
            #pragma unroll
            for (int rl = 0; rl < 8; rl++) {
                float c = coef[rl][k];
                acc[rl] = fmaf(c, pv, acc[rl]);
                axv[rl] = fmaxf(axv[rl], fmaf(c, pv, nk));
            }
        }
        float maxm2 = g_maxm[o*Bc + b];
        #pragma unroll
        for (int rl = 0; rl < 8; rl++) {
            int r = r0 + rl;
            float fs   = g_cfsum[(s*Bc + b)*Lc + r];
            float mfac = g_maskf[(s*Bc + b)*Lc + r] * maxm2;
            g_attmean[((s*Bc + b)*Lc + r)*Hc + tid] = __fdividef(acc[rl], fmaxf(fs, EPSF));
            g_attmax [((s*Bc + b)*Lc + r)*Hc + tid] = axv[rl] * mfac;
        }
    }
}

// ---------------- K4: heavy pairwise multi-perspective (w1) ----------------
// grid (B, 16, 2); 160 threads = 8 i x 20 p. f32x2 packed FMA; occupancy 3.
__global__ __launch_bounds__(160, 3) void k4_pairwise(const float* __restrict__ w1,
                                                      float* __restrict__ out) {
    extern __shared__ float sm[];
    float* ch   = sm;                    // 128*104 (16B-aligned rows)
    float* r2   = ch + Lc*HPAD4;         // 128*20 reciprocal weighted norms (other side)
    float* m2f  = r2 + Lc*Pc;            // 128
    float* negj = m2f + Lc;              // 128
    float* v1t  = negj + Lc;             // 8*101
    int b = blockIdx.x, it = blockIdx.y, s = blockIdx.z, o = 1 - s;
    int tid = threadIdx.x;
    int i0 = it * 8;

    for (int idx = tid; idx < Lc*Hc; idx += 160) {
        int j = idx / Hc, h = idx - j*Hc;
        ch[j*HPAD4 + h] = g_v[((o*Bc + b)*Lc + j)*Hc + h];
    }
    for (int idx = tid; idx < Lc*Pc; idx += 160)
        r2[idx] = g_rnw[((size_t)(o*Bc + b)*Lc)*Pc + idx];
    if (tid < Lc) {
        float m = g_maskf[(o*Bc + b)*Lc + tid];
        m2f[tid]  = m;
        negj[tid] = (m > 0.f) ? 0.f : MINV;
    }
    for (int idx = tid; idx < 8*Hc; idx += 160) {
        int il = idx / Hc, h = idx - il*Hc;
        v1t[il*HPAD + h] = g_v[((s*Bc + b)*Lc + i0 + il)*Hc + h];
    }
    __syncthreads();

    int il = tid / Pc, p = tid - il*Pc;
    int i = i0 + il;
    float rnw1 = g_rnw[((s*Bc + b)*Lc + i)*Pc + p];

    unsigned long long wcp[50];
    #pragma unroll
    for (int q = 0; q < 50; q++) {
        float wa = __ldg(&w1[p*Hc + 2*q]);
        float wb = __ldg(&w1[p*Hc + 2*q + 1]);
        wcp[q] = pack2f(wa*wa*rnw1*v1t[il*HPAD + 2*q], wb*wb*rnw1*v1t[il*HPAD + 2*q + 1]);
    }
    float m1 = g_maskf[(s*Bc + b)*Lc + i];

    float vmax = MINV, vsum = 0.f;
    for (int j = 0; j < Lc; j++) {
        const ulonglong2* row = (const ulonglong2*)&ch[j*HPAD4];
        unsigned long long a0 = 0ull, a1 = 0ull, a2 = 0ull, a3 = 0ull;
        #pragma unroll
        for (int q = 0; q < 25; q++) {
            ulonglong2 cc = row[q];   // 4 floats of ch[j]
            if (q & 1) { fma2(a2, wcp[2*q], cc.x); fma2(a3, wcp[2*q + 1], cc.y); }
            else       { fma2(a0, wcp[2*q], cc.x); fma2(a1, wcp[2*q + 1], cc.y); }
        }
        float dot = sum2f(add2(add2(a0, a1), add2(a2, a3)));
        float val = dot * r2[j*Pc + p];
        vsum = fmaf(val, m2f[j], vsum);
        vmax = fmaxf(vmax, val + negj[j]);
    }
    float* orow = out + (size_t)s*(Bc*Lc*NCOL) + (size_t)(b*Lc + i)*NCOL;
    orow[23 + p] = vmax * (m1 * g_maxm[o*Bc + b]);
    orow[43 + p] = (m1 * vsum) / fmaxf(m1 * g_cnt[o*Bc + b], EPSF);
}

// ---------------- K5: final cos-sims + remaining 65 columns ----------------
// grid (B, 2, 8); 336 threads = 16 i x 21 slots (slot 0 = unweighted, 1..20 = p).
__global__ __launch_bounds__(336) void k5_final(const float* __restrict__ w0,
                                                const float* __restrict__ w2,
                                                const float* __restrict__ w3,
                                                float* __restrict__ out) {
    int b = blockIdx.x, s = blockIdx.y, it = blockIdx.z, o = 1 - s;
    int i0 = it * 16;
    int tid = threadIdx.x;

    __shared__ float v1t[16][HPAD];
    __shared__ float amn[16][HPAD];
    __shared__ float amx[16][HPAD];
    __shared__ float lastv[Hc];
    __shared__ float wsq[3][Hc][Pc];

    for (int idx = tid; idx < 16*Hc; idx += 336) {
        int il = idx / Hc, h = idx - il*Hc;
        int base = ((s*Bc + b)*Lc + i0 + il)*Hc + h;
        v1t[il][h] = g_v[base];
        amn[il][h] = g_attmean[base];
        amx[il][h] = g_attmax[base];
    }
    for (int idx = tid; idx < Hc; idx += 336) lastv[idx] = g_last[(o*Bc + b)*Hc + idx];
    for (int idx = tid; idx < 3*Hc*Pc; idx += 336) {
        int pr = idx / (Hc*Pc);
        int r2i = idx - pr*(Hc*Pc);
        int h = r2i / Pc, p = r2i - h*Pc;
        const float* w = (pr == 0) ? w0 : ((pr == 1) ? w2 : w3);
        float wv = w[p*Hc + h];
        wsq[pr][h][p] = wv*wv;
    }
    __syncthreads();

    int il = tid / 21, q = tid - il*21;
    int i = i0 + il;
    float m1    = g_maskf[(s*Bc + b)*Lc + i];
    float cnt2  = g_cnt[o*Bc + b];
    float maxm2 = g_maxm[o*Bc + b];
    float* orow = out + (size_t)s*(Bc*Lc*NCOL) + (size_t)(b*Lc + i)*NCOL;

    if (q == 0) {
        orow[0] = g_cmax[(s*Bc + b)*Lc + i] * (m1 * maxm2);
        orow[1] = (m1 * g_cmsum[(s*Bc + b)*Lc + i]) / fmaxf(m1 * cnt2, EPSF);
    }

    #pragma unroll
    for (int pr = 0; pr < 3; pr++) {
        const float* part = (pr == 0) ? lastv : ((pr == 1) ? &amn[il][0] : &amx[il][0]);
        float saa = 0.f, sab = 0.f, sbb = 0.f;
        if (q == 0) {
            #pragma unroll 4
            for (int h = 0; h < Hc; h++) {
                float a = v1t[il][h], bv = part[h];
                sab = fmaf(a, bv, sab);
                saa = fmaf(a, a, saa);
                sbb = fmaf(bv, bv, sbb);
            }
        } else {
            int p = q - 1;
            #pragma unroll 4
            for (int h = 0; h < Hc; h++) {
                float a = v1t[il][h], bv = part[h], w = wsq[pr][h][p];
                sab = fmaf(w, a*bv, sab);
                saa = fmaf(w, a*a, saa);
                sbb = fmaf(w, bv*bv, sbb);
            }
        }
        float val = sab / (fmaxf(sqrtf(saa), EPSF) * fmaxf(sqrtf(sbb), EPSF));
        int col = (pr == 0) ? ((q == 0) ? 2 : 3 + (q - 1))
                : (pr == 1) ? ((q == 0) ? 63 : 64 + (q - 1))
                :             ((q == 0) ? 84 : 85 + (q - 1));
        orow[col] = val;
    }
}

// ---------------- launch ----------------
extern "C" void kernel_launch(void* const* d_in, const int* in_sizes, int n_in,
                              void* d_out, int out_size) {
    const float* ctxp  = (const float*)d_in[0];
    const int*   maskp = (const int*)  d_in[1];
    const float* ctxh  = (const float*)d_in[2];
    const int*   maskh = (const int*)  d_in[3];
    const float* w0    = (const float*)d_in[4];
    const float* w1    = (const float*)d_in[5];
    const float* w2    = (const float*)d_in[6];
    const float* w3    = (const float*)d_in[7];
    float* out = (float*)d_out;

    const int SM1 = (Lc*HPAD + 3*Lc + 8*HPAD + Lc*9) * 4;           // ~61 KB
    const int SM4 = (Lc*HPAD4 + Lc*Pc + 2*Lc + 8*HPAD) * 4;         // ~67.7 KB
    cudaFuncSetAttribute(k1_cos,      cudaFuncAttributeMaxDynamicSharedMemorySize, SM1);
    cudaFuncSetAttribute(k4_pairwise, cudaFuncAttributeMaxDynamicSharedMemorySize, SM4);

    k0_prep<<<dim3(Bc, 2), Lc>>>(ctxp, maskp, ctxh, maskh, w1);
    k1_cos<<<dim3(Bc, 16), 256, SM1>>>();
    k2_colstats<<<Bc, Lc>>>();
    k3_att<<<dim3(Bc, 16, 2), Lc>>>();
    k4_pairwise<<<dim3(Bc, 16, 2), 160, SM4>>>(w1, out);
    k5_final<<<dim3(Bc, 2, 8), 336>>>(w0, w2, w3, out);
}

// round 4
// speedup vs baseline: 1.6961x; 1.5808x over previous
#include <cuda_runtime.h>

#define Bc 32
#define Lc 128
#define Hc 100
#define Pc 20
#define HPAD 101
#define NCOL 105
#define EPSF 1e-8f
#define MINV -1e7f
#define KC 25

// ---------------- scratch (device globals; no allocation allowed) ----------------
__device__ float g_v[2*Bc*Lc*Hc];        // masked vectors, [side][b][i][h]
__device__ float g_vT[2*Bc*Hc*Lc];       // transposed: [side][b][h][i]
__device__ float g_rnorm[2*Bc*Lc];       // 1/max(norm, eps)
__device__ float g_maskf[2*Bc*Lc];
__device__ float g_rnw[2*Bc*Lc*Pc];      // 1/max(||w1[p]*v_i||, eps)
__device__ float g_cnt[2*Bc];
__device__ float g_maxm[2*Bc];
__device__ float g_last[2*Bc*Hc];
__device__ float g_cos[Bc*Lc*Lc];        // [b][i][j]
__device__ float g_cosT[Bc*Lc*Lc];       // [b][j][i]
__device__ float g_cmax[2*Bc*Lc];
__device__ float g_cmsum[2*Bc*Lc];
__device__ float g_cfsum[2*Bc*Lc];
__device__ float g_attmean[2*Bc*Lc*Hc];
__device__ float g_attmax[2*Bc*Lc*Hc];

// ---------------- f32x2 packed math helpers ----------------
__device__ __forceinline__ void fma2(unsigned long long &acc, unsigned long long a, unsigned long long b){
    asm("fma.rn.f32x2 %0, %1, %2, %0;" : "+l"(acc) : "l"(a), "l"(b));
}
__device__ __forceinline__ unsigned long long pack2f(float lo, float hi){
    unsigned long long r; asm("mov.b64 %0, {%1,%2};" : "=l"(r) : "f"(lo), "f"(hi)); return r;
}
__device__ __forceinline__ void unpack2(float &lo, float &hi, unsigned long long v){
    asm("mov.b64 {%0,%1}, %2;" : "=f"(lo), "=f"(hi) : "l"(v));
}

// ---------------- K0: mask, reciprocal norms, weighted norms, counts, last, transpose ----------------
__global__ void k0_prep(const float* __restrict__ ctxp, const int* __restrict__ maskp,
                        const float* __restrict__ ctxh, const int* __restrict__ maskh,
                        const float* __restrict__ w1) {
    int b = blockIdx.x, s = blockIdx.y;
    int i = threadIdx.x;
    const float* ctx = (s == 0) ? ctxp : ctxh;
    const int*   mk  = (s == 0) ? maskp : maskh;
    int mi = mk[b*Lc + i];
    float m = (float)mi;

    float x[Hc];
    float ssq = 0.f;
    const float* src = ctx + (size_t)(b*Lc + i)*Hc;
    #pragma unroll
    for (int h = 0; h < Hc; h++) {
        float t = src[h] * m;
        x[h] = t; ssq += t*t;
        g_v[((s*Bc + b)*Lc + i)*Hc + h] = t;
    }
    g_rnorm[(s*Bc + b)*Lc + i] = 1.0f / fmaxf(sqrtf(ssq), EPSF);
    g_maskf[(s*Bc + b)*Lc + i] = m;

    for (int p = 0; p < Pc; p++) {
        float acc = 0.f;
        #pragma unroll
        for (int h = 0; h < Hc; h++) {
            float w = __ldg(&w1[p*Hc + h]);
            float t = w * x[h];
            acc += t*t;
        }
        g_rnw[((s*Bc + b)*Lc + i)*Pc + p] = 1.0f / fmaxf(sqrtf(acc), EPSF);
    }

    // transpose to g_vT via smem, two passes of 50 h-rows
    __shared__ float tb[50][Lc];
    #pragma unroll
    for (int hp = 0; hp < 2; hp++) {
        __syncthreads();
        #pragma unroll
        for (int r = 0; r < 50; r++) tb[r][i] = x[hp*50 + r];
        __syncthreads();
        for (int r = 0; r < 50; r++)
            g_vT[((size_t)(s*Bc + b)*Hc + hp*50 + r)*Lc + i] = tb[r][i];
    }

    __shared__ int scnt, smax, sidx;
    if (i == 0) { scnt = 0; smax = 0; }
    __syncthreads();
    atomicAdd(&scnt, mi);
    atomicMax(&smax, mi);
    __syncthreads();
    if (i == 0) {
        g_cnt[s*Bc + b]  = (float)scnt;
        g_maxm[s*Bc + b] = (float)smax;
        sidx = (scnt > 0) ? scnt - 1 : 0;
    }
    __syncthreads();
    if (i < Hc) g_last[(s*Bc + b)*Hc + i] = g_v[((s*Bc + b)*Lc + sidx)*Hc + i];
}

// ---------------- K1: cos matrix (+transpose) + p-side row stats ----------------
__global__ void k1_cos() {
    extern __shared__ float sm[];
    float* ch   = sm;                  // 128*101
    float* rnh  = ch + Lc*HPAD;        // 128
    float* mh   = rnh + Lc;            // 128
    float* negj = mh + Lc;             // 128
    float* cp   = negj + Lc;           // 8*101
    float* cs   = cp + 8*HPAD;         // 128*9 (transpose staging)
    int b = blockIdx.x;
    int i0 = blockIdx.y * 8;
    int tid = threadIdx.x;

    for (int idx = tid; idx < Lc*Hc; idx += 256) {
        int j = idx / Hc, h = idx - j*Hc;
        ch[j*HPAD + h] = g_v[((1*Bc + b)*Lc + j)*Hc + h];
    }
    for (int idx = tid; idx < 8*Hc; idx += 256) {
        int il = idx / Hc, h = idx - il*Hc;
        cp[il*HPAD + h] = g_v[((0*Bc + b)*Lc + i0 + il)*Hc + h];
    }
    if (tid < Lc) {
        rnh[tid] = g_rnorm[(1*Bc + b)*Lc + tid];
        float m  = g_maskf[(1*Bc + b)*Lc + tid];
        mh[tid]  = m;
        negj[tid] = (m > 0.f) ? 0.f : MINV;
    }
    __syncthreads();

    int g = tid >> 5, lane = tid & 31;
    int i = i0 + g;
    float rni = g_rnorm[(0*Bc + b)*Lc + i];
    float vmax = MINV, msum = 0.f, fsum = 0.f;

    for (int jj = 0; jj < 4; jj++) {
        int j = jj*32 + lane;
        float a0=0.f, a1=0.f, a2=0.f, a3=0.f;
        #pragma unroll
        for (int h = 0; h < Hc; h += 4) {
            a0 += cp[g*HPAD + h+0] * ch[j*HPAD + h+0];
            a1 += cp[g*HPAD + h+1] * ch[j*HPAD + h+1];
            a2 += cp[g*HPAD + h+2] * ch[j*HPAD + h+2];
            a3 += cp[g*HPAD + h+3] * ch[j*HPAD + h+3];
        }
        float dot = (a0+a1)+(a2+a3);
        float c = dot * rni * rnh[j];
        g_cos[(b*Lc + i)*Lc + j] = c;
        cs[j*9 + g] = c;
        fsum += c;
        msum = fmaf(c, mh[j], msum);
        vmax = fmaxf(vmax, c + negj[j]);
    }
    #pragma unroll
    for (int o = 16; o; o >>= 1) {
        vmax = fmaxf(vmax, __shfl_xor_sync(0xffffffffu, vmax, o));
        msum += __shfl_xor_sync(0xffffffffu, msum, o);
        fsum += __shfl_xor_sync(0xffffffffu, fsum, o);
    }
    if (lane == 0) {
        g_cmax[(0*Bc + b)*Lc + i]  = vmax;
        g_cmsum[(0*Bc + b)*Lc + i] = msum;
        g_cfsum[(0*Bc + b)*Lc + i] = fsum;
    }
    __syncthreads();
    if (tid < Lc) {
        int j = tid;
        float4 v0, v1;
        v0.x = cs[j*9+0]; v0.y = cs[j*9+1]; v0.z = cs[j*9+2]; v0.w = cs[j*9+3];
        v1.x = cs[j*9+4]; v1.y = cs[j*9+5]; v1.z = cs[j*9+6]; v1.w = cs[j*9+7];
        float4* dst = reinterpret_cast<float4*>(&g_cosT[(b*Lc + j)*Lc + i0]);
        dst[0] = v0; dst[1] = v1;
    }
}

// ---------------- K2: h-side column stats of cos ----------------
__global__ void k2_colstats() {
    int b = blockIdx.x, j = threadIdx.x;
    __shared__ float mp[Lc], negp[Lc];
    float m = g_maskf[(0*Bc + b)*Lc + j];
    mp[j] = m;
    negp[j] = (m > 0.f) ? 0.f : MINV;
    __syncthreads();
    float vmax = MINV, msum = 0.f, fsum = 0.f;
    #pragma unroll 4
    for (int i = 0; i < Lc; i++) {
        float v = g_cos[(b*Lc + i)*Lc + j];
        fsum += v;
        msum = fmaf(v, mp[i], msum);
        vmax = fmaxf(vmax, v + negp[i]);
    }
    g_cmax[(1*Bc + b)*Lc + j]  = vmax;
    g_cmsum[(1*Bc + b)*Lc + j] = msum;
    g_cfsum[(1*Bc + b)*Lc + j] = fsum;
}

// ---------------- K3: attentive mean + max-attentive vectors ----------------
__global__ void k3_att() {
    int b = blockIdx.x, r0 = blockIdx.y * 8, s = blockIdx.z, o = 1 - s;
    int tid = threadIdx.x; // 128
    __shared__ float coef[8][Lc];
    __shared__ float negk[Lc];

    const float* src = (s == 0) ? g_cos : g_cosT;
    #pragma unroll
    for (int rl = 0; rl < 8; rl++)
        coef[rl][tid] = src[(b*Lc + r0 + rl)*Lc + tid];
    negk[tid] = (g_maskf[(o*Bc + b)*Lc + tid] > 0.f) ? 0.f : MINV;
    __syncthreads();

    if (tid < Hc) {
        float acc[8], axv[8];
        #pragma unroll
        for (int rl = 0; rl < 8; rl++) { acc[rl] = 0.f; axv[rl] = MINV; }
        const float* vbase = &g_v[((size_t)(o*Bc + b)*Lc)*Hc + tid];
        for (int k = 0; k < Lc; k++) {
            float pv = __ldg(vbase + k*Hc);
            float nk = negk[k];
            #pragma unroll
            for (int rl = 0; rl < 8; rl++) {
                float c = coef[rl][k];
                acc[rl] = fmaf(c, pv, acc[rl]);
                axv[rl] = fmaxf(axv[rl], fmaf(c, pv, nk));
            }
        }
        float maxm2 = g_maxm[o*Bc + b];
        #pragma unroll
        for (int rl = 0; rl < 8; rl++) {
            int r = r0 + rl;
            float fs   = g_cfsum[(s*Bc + b)*Lc + r];
            float mfac = g_maskf[(s*Bc + b)*Lc + r] * maxm2;
            g_attmean[((s*Bc + b)*Lc + r)*Hc + tid] = __fdividef(acc[rl], fmaxf(fs, EPSF));
            g_attmax [((s*Bc + b)*Lc + r)*Hc + tid] = axv[rl] * mfac;
        }
    }
}

// ---------------- K4: symmetric pairwise multi-perspective GEMM ----------------
// One block per (b, p). C[i,j] = sum_h (w1[p,h]^2 * v1[i,h] * rnw1[i,p]) * v2[j,h],
// computed ONCE; row reductions (over j) give mv_p, column reductions give mv_h.
// 256 threads = 16x16, each owns an 8x8 register tile with f32x2 packed FMA.
__global__ __launch_bounds__(256, 2) void k4_sym(const float* __restrict__ w1,
                                                 float* __restrict__ out) {
    __shared__ float wsq[Hc];
    __shared__ float rnw1s[Lc], rnw2s[Lc];
    __shared__ float negj[Lc], m2j[Lc], negi[Lc], m1i[Lc];
    __shared__ float stage[2*KC*132];    // aT | bT ; reused for reductions

    int b = blockIdx.x, p = blockIdx.y;
    int tid = threadIdx.x;
    int tx = tid & 15, ty = tid >> 4;

    for (int idx = tid; idx < Hc; idx += 256) {
        float w = __ldg(&w1[p*Hc + idx]);
        wsq[idx] = w*w;
    }
    if (tid < Lc) {
        rnw1s[tid] = g_rnw[((0*Bc + b)*Lc + tid)*Pc + p];
        rnw2s[tid] = g_rnw[((1*Bc + b)*Lc + tid)*Pc + p];
        float mh = g_maskf[(1*Bc + b)*Lc + tid];
        m2j[tid] = mh; negj[tid] = (mh > 0.f) ? 0.f : MINV;
        float mp = g_maskf[(0*Bc + b)*Lc + tid];
        m1i[tid] = mp; negi[tid] = (mp > 0.f) ? 0.f : MINV;
    }

    unsigned long long acc[8][4];
    #pragma unroll
    for (int r = 0; r < 8; r++)
        #pragma unroll
        for (int c = 0; c < 4; c++) acc[r][c] = 0ull;

    float* aT = stage;               // [KC][132]
    float* bT = stage + KC*132;      // [KC][132]
    const float* vT0 = &g_vT[((size_t)(0*Bc + b)*Hc)*Lc];
    const float* vT1 = &g_vT[((size_t)(1*Bc + b)*Hc)*Lc];

    for (int kc = 0; kc < 4; kc++) {
        __syncthreads();
        // stage chunk: coalesced global reads, conflict-free smem writes
        for (int idx = tid; idx < KC*Lc; idx += 256) {
            int kk = idx >> 7, i = idx & 127;
            int k = kc*KC + kk;
            aT[kk*132 + i] = wsq[k] * vT0[(size_t)k*Lc + i] * rnw1s[i];
            bT[kk*132 + i] = vT1[(size_t)k*Lc + i];
        }
        __syncthreads();
        #pragma unroll 5
        for (int kk = 0; kk < KC; kk++) {
            float4 a0 = *reinterpret_cast<const float4*>(&aT[kk*132 + ty*8]);
            float4 a1 = *reinterpret_cast<const float4*>(&aT[kk*132 + ty*8 + 4]);
            ulonglong2 b0 = *reinterpret_cast<const ulonglong2*>(&bT[kk*132 + tx*8]);
            ulonglong2 b1 = *reinterpret_cast<const ulonglong2*>(&bT[kk*132 + tx*8 + 4]);
            unsigned long long ad[8];
            ad[0] = pack2f(a0.x, a0.x); ad[1] = pack2f(a0.y, a0.y);
            ad[2] = pack2f(a0.z, a0.z); ad[3] = pack2f(a0.w, a0.w);
            ad[4] = pack2f(a1.x, a1.x); ad[5] = pack2f(a1.y, a1.y);
            ad[6] = pack2f(a1.z, a1.z); ad[7] = pack2f(a1.w, a1.w);
            #pragma unroll
            for (int r = 0; r < 8; r++) {
                fma2(acc[r][0], ad[r], b0.x);
                fma2(acc[r][1], ad[r], b0.y);
                fma2(acc[r][2], ad[r], b1.x);
                fma2(acc[r][3], ad[r], b1.y);
            }
        }
    }
    __syncthreads();

    // per-thread reductions of the 8x8 tile
    float rmax[8], rsum[8], cmax[8], csum[8];
    #pragma unroll
    for (int r = 0; r < 8; r++) { rmax[r] = MINV; rsum[r] = 0.f; cmax[r] = MINV; csum[r] = 0.f; }
    #pragma unroll
    for (int r = 0; r < 8; r++) {
        int i = ty*8 + r;
        float ni = negi[i], mi = m1i[i];
        #pragma unroll
        for (int c4 = 0; c4 < 4; c4++) {
            float v0, v1; unpack2(v0, v1, acc[r][c4]);
            int j0 = tx*8 + c4*2;
            float val0 = v0 * rnw2s[j0];
            float val1 = v1 * rnw2s[j0+1];
            rmax[r] = fmaxf(rmax[r], val0 + negj[j0]);
            rmax[r] = fmaxf(rmax[r], val1 + negj[j0+1]);
            rsum[r] = fmaf(val0, m2j[j0], rsum[r]);
            rsum[r] = fmaf(val1, m2j[j0+1], rsum[r]);
            cmax[c4*2]   = fmaxf(cmax[c4*2],   val0 + ni);
            cmax[c4*2+1] = fmaxf(cmax[c4*2+1], val1 + ni);
            csum[c4*2]   = fmaf(val0, mi, csum[c4*2]);
            csum[c4*2+1] = fmaf(val1, mi, csum[c4*2+1]);
        }
    }

    // ---- rows (mv_p, side 0): reduce across tx ----
    float* bufA = stage;            // [128][17]
    float* bufB = stage + 128*17;   // [128][17]
    #pragma unroll
    for (int r = 0; r < 8; r++) {
        int i = ty*8 + r;
        bufA[i*17 + tx] = rmax[r];
        bufB[i*17 + tx] = rsum[r];
    }
    __syncthreads();
    if (tid < Lc) {
        int i = tid;
        float vm = MINV, vs = 0.f;
        #pragma unroll
        for (int t = 0; t < 16; t++) {
            vm = fmaxf(vm, bufA[i*17 + t]);
            vs += bufB[i*17 + t];
        }
        float m1 = m1i[i];
        float* orow = out + (size_t)(b*Lc + i)*NCOL;
        orow[23 + p] = vm * (m1 * g_maxm[1*Bc + b]);
        orow[43 + p] = (m1 * vs) / fmaxf(m1 * g_cnt[1*Bc + b], EPSF);
    }
    __syncthreads();

    // ---- cols (mv_h, side 1): reduce across ty ----
    #pragma unroll
    for (int c = 0; c < 8; c++) {
        int j = tx*8 + c;
        bufA[j*17 + ty] = cmax[c];
        bufB[j*17 + ty] = csum[c];
    }
    __syncthreads();
    if (tid < Lc) {
        int j = tid;
        float vm = MINV, vs = 0.f;
        #pragma unroll
        for (int t = 0; t < 16; t++) {
            vm = fmaxf(vm, bufA[j*17 + t]);
            vs += bufB[j*17 + t];
        }
        float mh = m2j[j];
        float* orow = out + (size_t)(Bc*Lc*NCOL) + (size_t)(b*Lc + j)*NCOL;
        orow[23 + p] = vm * (mh * g_maxm[0*Bc + b]);
        orow[43 + p] = (mh * vs) / fmaxf(mh * g_cnt[0*Bc + b], EPSF);
    }
}

// ---------------- K5: final cos-sims + remaining 65 columns ----------------
__global__ __launch_bounds__(336) void k5_final(const float* __restrict__ w0,
                                                const float* __restrict__ w2,
                                                const float* __restrict__ w3,
                                                float* __restrict__ out) {
    int b = blockIdx.x, s = blockIdx.y, it = blockIdx.z, o = 1 - s;
    int i0 = it * 16;
    int tid = threadIdx.x;

    __shared__ float v1t[16][HPAD];
    __shared__ float amn[16][HPAD];
    __shared__ float amx[16][HPAD];
    __shared__ float lastv[Hc];
    __shared__ float wsq[3][Hc][Pc];

    for (int idx = tid; idx < 16*Hc; idx += 336) {
        int il = idx / Hc, h = idx - il*Hc;
        int base = ((s*Bc + b)*Lc + i0 + il)*Hc + h;
        v1t[il][h] = g_v[base];
        amn[il][h] = g_attmean[base];
        amx[il][h] = g_attmax[base];
    }
    for (int idx = tid; idx < Hc; idx += 336) lastv[idx] = g_last[(o*Bc + b)*Hc + idx];
    for (int idx = tid; idx < 3*Hc*Pc; idx += 336) {
        int pr = idx / (Hc*Pc);
        int r2i = idx - pr*(Hc*Pc);
        int h = r2i / Pc, p = r2i - h*Pc;
        const float* w = (pr == 0) ? w0 : ((pr == 1) ? w2 : w3);
        float wv = w[p*Hc + h];
        wsq[pr][h][p] = wv*wv;
    }
    __syncthreads();

    int il = tid / 21, q = tid - il*21;
    int i = i0 + il;
    float m1    = g_maskf[(s*Bc + b)*Lc + i];
    float cnt2  = g_cnt[o*Bc + b];
    float maxm2 = g_maxm[o*Bc + b];
    float* orow = out + (size_t)s*(Bc*Lc*NCOL) + (size_t)(b*Lc + i)*NCOL;

    if (q == 0) {
        orow[0] = g_cmax[(s*Bc + b)*Lc + i] * (m1 * maxm2);
        orow[1] = (m1 * g_cmsum[(s*Bc + b)*Lc + i]) / fmaxf(m1 * cnt2, EPSF);
    }

    #pragma unroll
    for (int pr = 0; pr < 3; pr++) {
        const float* part = (pr == 0) ? lastv : ((pr == 1) ? &amn[il][0] : &amx[il][0]);
        float saa = 0.f, sab = 0.f, sbb = 0.f;
        if (q == 0) {
            #pragma unroll 4
            for (int h = 0; h < Hc; h++) {
                float a = v1t[il][h], bv = part[h];
                sab = fmaf(a, bv, sab);
                saa = fmaf(a, a, saa);
                sbb = fmaf(bv, bv, sbb);
            }
        } else {
            int p = q - 1;
            #pragma unroll 4
            for (int h = 0; h < Hc; h++) {
                float a = v1t[il][h], bv = part[h], w = wsq[pr][h][p];
                sab = fmaf(w, a*bv, sab);
                saa = fmaf(w, a*a, saa);
                sbb = fmaf(w, bv*bv, sbb);
            }
        }
        float val = sab / (fmaxf(sqrtf(saa), EPSF) * fmaxf(sqrtf(sbb), EPSF));
        int col = (pr == 0) ? ((q == 0) ? 2 : 3 + (q - 1))
                : (pr == 1) ? ((q == 0) ? 63 : 64 + (q - 1))
                :             ((q == 0) ? 84 : 85 + (q - 1));
        orow[col] = val;
    }
}

// ---------------- launch ----------------
extern "C" void kernel_launch(void* const* d_in, const int* in_sizes, int n_in,
                              void* d_out, int out_size) {
    const float* ctxp  = (const float*)d_in[0];
    const int*   maskp = (const int*)  d_in[1];
    const float* ctxh  = (const float*)d_in[2];
    const int*   maskh = (const int*)  d_in[3];
    const float* w0    = (const float*)d_in[4];
    const float* w1    = (const float*)d_in[5];
    const float* w2    = (const float*)d_in[6];
    const float* w3    = (const float*)d_in[7];
    float* out = (float*)d_out;

    const int SM1 = (Lc*HPAD + 3*Lc + 8*HPAD + Lc*9) * 4;
    cudaFuncSetAttribute(k1_cos, cudaFuncAttributeMaxDynamicSharedMemorySize, SM1);

    // order chosen so the ncu capture slot (4th launch) lands on k4_sym
    k0_prep<<<dim3(Bc, 2), Lc>>>(ctxp, maskp, ctxh, maskh, w1);
    k1_cos<<<dim3(Bc, 16), 256, SM1>>>();
    k2_colstats<<<Bc, Lc>>>();
    k4_sym<<<dim3(Bc, Pc), 256>>>(w1, out);
    k3_att<<<dim3(Bc, 16, 2), Lc>>>();
    k5_final<<<dim3(Bc, 2, 8), 336>>>(w0, w2, w3, out);
}

// round 5
// speedup vs baseline: 1.9865x; 1.1712x over previous
#include <cuda_runtime.h>

#define Bc 32
#define Lc 128
#define Hc 100
#define Pc 20
#define HPAD 101
#define NCOL 105
#define EPSF 1e-8f
#define MINV -1e7f

// ---------------- scratch (device globals; no allocation allowed) ----------------
__device__ float g_v[2*Bc*Lc*Hc];        // masked vectors, [side][b][i][h]
__device__ float g_vT[2*Bc*Hc*Lc];       // transposed: [side][b][h][i]
__device__ float g_rnorm[2*Bc*Lc];       // 1/max(norm, eps)
__device__ float g_maskf[2*Bc*Lc];
__device__ float g_rnw[2*Bc*Lc*Pc];      // 1/max(||w1[p]*v_i||, eps)
__device__ float g_cnt[2*Bc];
__device__ float g_maxm[2*Bc];
__device__ float g_last[2*Bc*Hc];
__device__ float g_cos[Bc*Lc*Lc];        // [b][i][j]
__device__ float g_cosT[Bc*Lc*Lc];       // [b][j][i]
__device__ float g_cmax[2*Bc*Lc];
__device__ float g_cmsum[2*Bc*Lc];
__device__ float g_cfsum[2*Bc*Lc];
__device__ float g_attmean[2*Bc*Lc*Hc];
__device__ float g_attmax[2*Bc*Lc*Hc];
__device__ float g_prmax[2*Bc*Lc*Pc];    // k4 row-partial max  [z][b][i][p]
__device__ float g_prsum[2*Bc*Lc*Pc];    // k4 row-partial sum

// ---------------- f32x2 packed math helpers ----------------
__device__ __forceinline__ void fma2(unsigned long long &acc, unsigned long long a, unsigned long long b){
    asm("fma.rn.f32x2 %0, %1, %2, %0;" : "+l"(acc) : "l"(a), "l"(b));
}
__device__ __forceinline__ unsigned long long pack2f(float lo, float hi){
    unsigned long long r; asm("mov.b64 %0, {%1,%2};" : "=l"(r) : "f"(lo), "f"(hi)); return r;
}
__device__ __forceinline__ void unpack2(float &lo, float &hi, unsigned long long v){
    asm("mov.b64 {%0,%1}, %2;" : "=f"(lo), "=f"(hi) : "l"(v));
}

// ---------------- K0: prep (coalesced staging + parallel rnw) ----------------
// grid (Bc, 2), 256 threads, dynamic smem: xs[128][101] + wsqT[100][20] + m[128]
__global__ __launch_bounds__(256) void k0_prep(const float* __restrict__ ctxp, const int* __restrict__ maskp,
                                               const float* __restrict__ ctxh, const int* __restrict__ maskh,
                                               const float* __restrict__ w1) {
    extern __shared__ float sm0[];
    float* xs   = sm0;                   // [128][101] raw context
    float* wsqT = xs + Lc*HPAD;          // [100][20]  w1^2 transposed
    float* mv   = wsqT + Hc*Pc;          // [128] mask float
    int b = blockIdx.x, s = blockIdx.y;
    int tid = threadIdx.x;
    const float* ctx = (s == 0) ? ctxp : ctxh;
    const int*   mk  = (s == 0) ? maskp : maskh;

    // coalesced stage of ctx rows
    for (int idx = tid; idx < Lc*Hc; idx += 256) {
        int i = idx / Hc, h = idx - i*Hc;
        xs[i*HPAD + h] = ctx[(size_t)b*Lc*Hc + idx];
    }
    for (int idx = tid; idx < Pc*Hc; idx += 256) {
        int p = idx / Hc, h = idx - p*Hc;
        float w = __ldg(&w1[idx]);
        wsqT[h*Pc + p] = w*w;
    }
    __shared__ int scnt, smax, sidx;
    if (tid == 0) { scnt = 0; smax = 0; }
    __syncthreads();
    int mi = 0;
    if (tid < Lc) {
        mi = mk[b*Lc + tid];
        mv[tid] = (float)mi;
        atomicAdd(&scnt, mi);
        atomicMax(&smax, mi);
        g_maskf[(s*Bc + b)*Lc + tid] = (float)mi;
    }
    __syncthreads();
    if (tid == 0) {
        g_cnt[s*Bc + b]  = (float)scnt;
        g_maxm[s*Bc + b] = (float)smax;
        sidx = (scnt > 0) ? scnt - 1 : 0;
    }

    // masked g_v (coalesced)
    for (int idx = tid; idx < Lc*Hc; idx += 256) {
        int i = idx / Hc, h = idx - i*Hc;
        g_v[(size_t)(s*Bc + b)*Lc*Hc + idx] = xs[i*HPAD + h] * mv[i];
    }
    // masked g_vT (coalesced writes, conflict-free smem reads)
    for (int idx = tid; idx < Hc*Lc; idx += 256) {
        int h = idx >> 7, i = idx & 127;
        g_vT[((size_t)(s*Bc + b)*Hc + h)*Lc + i] = xs[i*HPAD + h] * mv[i];
    }
    // rnorm
    if (tid < Lc) {
        float ssq = 0.f;
        #pragma unroll 4
        for (int h = 0; h < Hc; h++) { float t = xs[tid*HPAD + h]; ssq = fmaf(t, t, ssq); }
        g_rnorm[(s*Bc + b)*Lc + tid] = 1.0f / fmaxf(sqrtf(ssq * mv[tid]), EPSF);
    }
    __syncthreads();
    // last token
    if (tid < Hc) g_last[(s*Bc + b)*Hc + tid] = xs[sidx*HPAD + tid] * mv[sidx];

    // rnw: thread = (token i, half of p)
    {
        int i = tid >> 1, hp = (tid & 1) * 10;
        float acc[10];
        #pragma unroll
        for (int p = 0; p < 10; p++) acc[p] = 0.f;
        #pragma unroll 2
        for (int h = 0; h < Hc; h++) {
            float xv = xs[i*HPAD + h];
            float xq = xv * xv;
            #pragma unroll
            for (int p = 0; p < 10; p++)
                acc[p] = fmaf(wsqT[h*Pc + hp + p], xq, acc[p]);
        }
        float m = mv[i];
        #pragma unroll
        for (int p = 0; p < 10; p++)
            g_rnw[((s*Bc + b)*Lc + i)*Pc + hp + p] = 1.0f / fmaxf(sqrtf(acc[p] * m), EPSF);
    }
}

// ---------------- K1: cos matrix (+transpose) + p-side row stats ----------------
__global__ void k1_cos() {
    extern __shared__ float sm[];
    float* ch   = sm;                  // 128*101
    float* rnh  = ch + Lc*HPAD;        // 128
    float* mh   = rnh + Lc;            // 128
    float* negj = mh + Lc;             // 128
    float* cp   = negj + Lc;           // 8*101
    float* cs   = cp + 8*HPAD;         // 128*9 (transpose staging)
    int b = blockIdx.x;
    int i0 = blockIdx.y * 8;
    int tid = threadIdx.x;

    for (int idx = tid; idx < Lc*Hc; idx += 256) {
        int j = idx / Hc, h = idx - j*Hc;
        ch[j*HPAD + h] = g_v[((1*Bc + b)*Lc + j)*Hc + h];
    }
    for (int idx = tid; idx < 8*Hc; idx += 256) {
        int il = idx / Hc, h = idx - il*Hc;
        cp[il*HPAD + h] = g_v[((0*Bc + b)*Lc + i0 + il)*Hc + h];
    }
    if (tid < Lc) {
        rnh[tid] = g_rnorm[(1*Bc + b)*Lc + tid];
        float m  = g_maskf[(1*Bc + b)*Lc + tid];
        mh[tid]  = m;
        negj[tid] = (m > 0.f) ? 0.f : MINV;
    }
    __syncthreads();

    int g = tid >> 5, lane = tid & 31;
    int i = i0 + g;
    float rni = g_rnorm[(0*Bc + b)*Lc + i];
    float vmax = MINV, msum = 0.f, fsum = 0.f;

    for (int jj = 0; jj < 4; jj++) {
        int j = jj*32 + lane;
        float a0=0.f, a1=0.f, a2=0.f, a3=0.f;
        #pragma unroll
        for (int h = 0; h < Hc; h += 4) {
            a0 += cp[g*HPAD + h+0] * ch[j*HPAD + h+0];
            a1 += cp[g*HPAD + h+1] * ch[j*HPAD + h+1];
            a2 += cp[g*HPAD + h+2] * ch[j*HPAD + h+2];
            a3 += cp[g*HPAD + h+3] * ch[j*HPAD + h+3];
        }
        float dot = (a0+a1)+(a2+a3);
        float c = dot * rni * rnh[j];
        g_cos[(b*Lc + i)*Lc + j] = c;
        cs[j*9 + g] = c;
        fsum += c;
        msum = fmaf(c, mh[j], msum);
        vmax = fmaxf(vmax, c + negj[j]);
    }
    #pragma unroll
    for (int o = 16; o; o >>= 1) {
        vmax = fmaxf(vmax, __shfl_xor_sync(0xffffffffu, vmax, o));
        msum += __shfl_xor_sync(0xffffffffu, msum, o);
        fsum += __shfl_xor_sync(0xffffffffu, fsum, o);
    }
    if (lane == 0) {
        g_cmax[(0*Bc + b)*Lc + i]  = vmax;
        g_cmsum[(0*Bc + b)*Lc + i] = msum;
        g_cfsum[(0*Bc + b)*Lc + i] = fsum;
    }
    __syncthreads();
    if (tid < Lc) {
        int j = tid;
        float4 v0, v1;
        v0.x = cs[j*9+0]; v0.y = cs[j*9+1]; v0.z = cs[j*9+2]; v0.w = cs[j*9+3];
        v1.x = cs[j*9+4]; v1.y = cs[j*9+5]; v1.z = cs[j*9+6]; v1.w = cs[j*9+7];
        float4* dst = reinterpret_cast<float4*>(&g_cosT[(b*Lc + j)*Lc + i0]);
        dst[0] = v0; dst[1] = v1;
    }
}

// ---------------- K2: h-side column stats of cos ----------------
__global__ void k2_colstats() {
    int b = blockIdx.x, j = threadIdx.x;
    __shared__ float mp[Lc], negp[Lc];
    float m = g_maskf[(0*Bc + b)*Lc + j];
    mp[j] = m;
    negp[j] = (m > 0.f) ? 0.f : MINV;
    __syncthreads();
    float vmax = MINV, msum = 0.f, fsum = 0.f;
    #pragma unroll 4
    for (int i = 0; i < Lc; i++) {
        float v = g_cos[(b*Lc + i)*Lc + j];
        fsum += v;
        msum = fmaf(v, mp[i], msum);
        vmax = fmaxf(vmax, v + negp[i]);
    }
    g_cmax[(1*Bc + b)*Lc + j]  = vmax;
    g_cmsum[(1*Bc + b)*Lc + j] = msum;
    g_cfsum[(1*Bc + b)*Lc + j] = fsum;
}

// ---------------- K3: attentive mean + max-attentive vectors ----------------
__global__ void k3_att() {
    int b = blockIdx.x, r0 = blockIdx.y * 8, s = blockIdx.z, o = 1 - s;
    int tid = threadIdx.x; // 128
    __shared__ float coef[8][Lc];
    __shared__ float negk[Lc];

    const float* src = (s == 0) ? g_cos : g_cosT;
    #pragma unroll
    for (int rl = 0; rl < 8; rl++)
        coef[rl][tid] = src[(b*Lc + r0 + rl)*Lc + tid];
    negk[tid] = (g_maskf[(o*Bc + b)*Lc + tid] > 0.f) ? 0.f : MINV;
    __syncthreads();

    if (tid < Hc) {
        float acc[8], axv[8];
        #pragma unroll
        for (int rl = 0; rl < 8; rl++) { acc[rl] = 0.f; axv[rl] = MINV; }
        const float* vbase = &g_v[((size_t)(o*Bc + b)*Lc)*Hc + tid];
        for (int k = 0; k < Lc; k++) {
            float pv = __ldg(vbase + k*Hc);
            float nk = negk[k];
            #pragma unroll
            for (int rl = 0; rl < 8; rl++) {
                float c = coef[rl][k];
                acc[rl] = fmaf(c, pv, acc[rl]);
                axv[rl] = fmaxf(axv[rl], fmaf(c, pv, nk));
            }
        }
        float maxm2 = g_maxm[o*Bc + b];
        #pragma unroll
        for (int rl = 0; rl < 8; rl++) {
            int r = r0 + rl;
            float fs   = g_cfsum[(s*Bc + b)*Lc + r];
            float mfac = g_maskf[(s*Bc + b)*Lc + r] * maxm2;
            g_attmean[((s*Bc + b)*Lc + r)*Hc + tid] = __fdividef(acc[rl], fmaxf(fs, EPSF));
            g_attmax [((s*Bc + b)*Lc + r)*Hc + tid] = axv[rl] * mfac;
        }
    }
}

// ---------------- K4: symmetric pairwise GEMM, j split in halves ----------------
// grid (Bc, Pc, 2): block = (b, p, j-half). C[i, j] = sum_h (wsq[p,h] v1[i,h]) v2[j,h];
// val = C * rnw1[i] * rnw2[j]. 256 threads = 16x16; tile = 4 i-pairs x 4 j (f32x2).
// Row (i) reductions partial -> g_prmax/g_prsum (k5 finalizes); col (j) complete -> out.
__global__ __launch_bounds__(256, 3) void k4_sym(const float* __restrict__ w1,
                                                 float* __restrict__ out) {
    __shared__ float wsq[Hc];
    __shared__ float rnw1s[Lc], negi[Lc], m1i[Lc];
    __shared__ float rnw2s[64], negj[64], m2j[64];
    __shared__ float aT[50*132];     // reused for reduction buffers
    __shared__ float bT[50*68];

    int b = blockIdx.x, p = blockIdx.y, z = blockIdx.z;
    int tid = threadIdx.x;
    int tx = tid & 15, ty = tid >> 4;
    int j0 = z * 64;

    for (int idx = tid; idx < Hc; idx += 256) {
        float w = __ldg(&w1[p*Hc + idx]);
        wsq[idx] = w*w;
    }
    if (tid < Lc) {
        rnw1s[tid] = g_rnw[((0*Bc + b)*Lc + tid)*Pc + p];
        float mp = g_maskf[(0*Bc + b)*Lc + tid];
        m1i[tid] = mp; negi[tid] = (mp > 0.f) ? 0.f : MINV;
    }
    if (tid < 64) {
        int j = j0 + tid;
        rnw2s[tid] = g_rnw[((1*Bc + b)*Lc + j)*Pc + p];
        float mh = g_maskf[(1*Bc + b)*Lc + j];
        m2j[tid] = mh; negj[tid] = (mh > 0.f) ? 0.f : MINV;
    }

    unsigned long long acc[4][4];
    #pragma unroll
    for (int r = 0; r < 4; r++)
        #pragma unroll
        for (int c = 0; c < 4; c++) acc[r][c] = 0ull;

    const float* vT0 = &g_vT[((size_t)(0*Bc + b)*Hc)*Lc];
    const float* vT1 = &g_vT[((size_t)(1*Bc + b)*Hc)*Lc];

    #pragma unroll 1
    for (int kc = 0; kc < 2; kc++) {
        __syncthreads();
        for (int idx = tid; idx < 50*Lc; idx += 256) {
            int kk = idx >> 7, i = idx & 127;
            int k = kc*50 + kk;
            aT[kk*132 + i] = wsq[k] * vT0[(size_t)k*Lc + i];
        }
        for (int idx = tid; idx < 50*64; idx += 256) {
            int kk = idx >> 6, jl = idx & 63;
            int k = kc*50 + kk;
            bT[kk*68 + jl] = vT1[(size_t)k*Lc + j0 + jl];
        }
        __syncthreads();
        #pragma unroll 10
        for (int kk = 0; kk < 50; kk++) {
            ulonglong2 a01 = *reinterpret_cast<const ulonglong2*>(&aT[kk*132 + ty*8]);
            ulonglong2 a23 = *reinterpret_cast<const ulonglong2*>(&aT[kk*132 + ty*8 + 4]);
            float4 bv = *reinterpret_cast<const float4*>(&bT[kk*68 + tx*4]);
            unsigned long long bd0 = pack2f(bv.x, bv.x);
            unsigned long long bd1 = pack2f(bv.y, bv.y);
            unsigned long long bd2 = pack2f(bv.z, bv.z);
            unsigned long long bd3 = pack2f(bv.w, bv.w);
            fma2(acc[0][0], a01.x, bd0); fma2(acc[0][1], a01.x, bd1);
            fma2(acc[0][2], a01.x, bd2); fma2(acc[0][3], a01.x, bd3);
            fma2(acc[1][0], a01.y, bd0); fma2(acc[1][1], a01.y, bd1);
            fma2(acc[1][2], a01.y, bd2); fma2(acc[1][3], a01.y, bd3);
            fma2(acc[2][0], a23.x, bd0); fma2(acc[2][1], a23.x, bd1);
            fma2(acc[2][2], a23.x, bd2); fma2(acc[2][3], a23.x, bd3);
            fma2(acc[3][0], a23.y, bd0); fma2(acc[3][1], a23.y, bd1);
            fma2(acc[3][2], a23.y, bd2); fma2(acc[3][3], a23.y, bd3);
        }
    }
    __syncthreads();

    // per-thread reductions of 8x4 tile
    float rmax[8], rsum[8], cmax[4], csum[4];
    #pragma unroll
    for (int r = 0; r < 8; r++) { rmax[r] = MINV; rsum[r] = 0.f; }
    #pragma unroll
    for (int c = 0; c < 4; c++) { cmax[c] = MINV; csum[c] = 0.f; }
    #pragma unroll
    for (int pr = 0; pr < 4; pr++) {
        int i0l = ty*8 + pr*2;
        float r1a = rnw1s[i0l], r1b = rnw1s[i0l+1];
        float nia = negi[i0l], nib = negi[i0l+1];
        float mia = m1i[i0l],  mib = m1i[i0l+1];
        #pragma unroll
        for (int c = 0; c < 4; c++) {
            float v0, v1; unpack2(v0, v1, acc[pr][c]);
            int jl = tx*4 + c;
            float rw2 = rnw2s[jl];
            float val0 = v0 * rw2 * r1a;
            float val1 = v1 * rw2 * r1b;
            rmax[pr*2]   = fmaxf(rmax[pr*2],   val0 + negj[jl]);
            rmax[pr*2+1] = fmaxf(rmax[pr*2+1], val1 + negj[jl]);
            rsum[pr*2]   = fmaf(val0, m2j[jl], rsum[pr*2]);
            rsum[pr*2+1] = fmaf(val1, m2j[jl], rsum[pr*2+1]);
            cmax[c] = fmaxf(cmax[c], val0 + nia);
            cmax[c] = fmaxf(cmax[c], val1 + nib);
            csum[c] = fmaf(val0, mia, csum[c]);
            csum[c] = fmaf(val1, mib, csum[c]);
        }
    }

    // ---- rows (mv_p partial): reduce across tx ----
    float* bufA = aT;
    float* bufB = aT + 128*17;
    #pragma unroll
    for (int r = 0; r < 8; r++) {
        int i = ty*8 + r;
        bufA[i*17 + tx] = rmax[r];
        bufB[i*17 + tx] = rsum[r];
    }
    __syncthreads();
    if (tid < Lc) {
        float vm = MINV, vs = 0.f;
        #pragma unroll
        for (int t = 0; t < 16; t++) {
            vm = fmaxf(vm, bufA[tid*17 + t]);
            vs += bufB[tid*17 + t];
        }
        g_prmax[((z*Bc + b)*Lc + tid)*Pc + p] = vm;
        g_prsum[((z*Bc + b)*Lc + tid)*Pc + p] = vs;
    }
    __syncthreads();

    // ---- cols (mv_h, complete): reduce across ty ----
    #pragma unroll
    for (int c = 0; c < 4; c++) {
        int jl = tx*4 + c;
        bufA[jl*17 + ty] = cmax[c];
        bufB[jl*17 + ty] = csum[c];
    }
    __syncthreads();
    if (tid < 64) {
        float vm = MINV, vs = 0.f;
        #pragma unroll
        for (int t = 0; t < 16; t++) {
            vm = fmaxf(vm, bufA[tid*17 + t]);
            vs += bufB[tid*17 + t];
        }
        int j = j0 + tid;
        float mh = m2j[tid];
        float* orow = out + (size_t)(Bc*Lc*NCOL) + (size_t)(b*Lc + j)*NCOL;
        orow[23 + p] = vm * (mh * g_maxm[0*Bc + b]);
        orow[43 + p] = (mh * vs) / fmaxf(mh * g_cnt[0*Bc + b], EPSF);
    }
}

// ---------------- K5: final cos-sims + remaining columns + mv_p finalize ----------------
__global__ __launch_bounds__(336) void k5_final(const float* __restrict__ w0,
                                                const float* __restrict__ w2,
                                                const float* __restrict__ w3,
                                                float* __restrict__ out) {
    int b = blockIdx.x, s = blockIdx.y, it = blockIdx.z, o = 1 - s;
    int i0 = it * 16;
    int tid = threadIdx.x;

    __shared__ float v1t[16][HPAD];
    __shared__ float amn[16][HPAD];
    __shared__ float amx[16][HPAD];
    __shared__ float lastv[Hc];
    __shared__ float wsq[3][Hc][Pc];

    for (int idx = tid; idx < 16*Hc; idx += 336) {
        int il = idx / Hc, h = idx - il*Hc;
        int base = ((s*Bc + b)*Lc + i0 + il)*Hc + h;
        v1t[il][h] = g_v[base];
        amn[il][h] = g_attmean[base];
        amx[il][h] = g_attmax[base];
    }
    for (int idx = tid; idx < Hc; idx += 336) lastv[idx] = g_last[(o*Bc + b)*Hc + idx];
    for (int idx = tid; idx < 3*Hc*Pc; idx += 336) {
        int pr = idx / (Hc*Pc);
        int r2i = idx - pr*(Hc*Pc);
        int h = r2i / Pc, p = r2i - h*Pc;
        const float* w = (pr == 0) ? w0 : ((pr == 1) ? w2 : w3);
        float wv = w[p*Hc + h];
        wsq[pr][h][p] = wv*wv;
    }
    __syncthreads();

    int il = tid / 21, q = tid - il*21;
    int i = i0 + il;
    float m1    = g_maskf[(s*Bc + b)*Lc + i];
    float cnt2  = g_cnt[o*Bc + b];
    float maxm2 = g_maxm[o*Bc + b];
    float* orow = out + (size_t)s*(Bc*Lc*NCOL) + (size_t)(b*Lc + i)*NCOL;

    if (q == 0) {
        orow[0] = g_cmax[(s*Bc + b)*Lc + i] * (m1 * maxm2);
        orow[1] = (m1 * g_cmsum[(s*Bc + b)*Lc + i]) / fmaxf(m1 * cnt2, EPSF);
    } else if (s == 0) {
        // finalize mv_p from k4 partials (two j-halves)
        int p = q - 1;
        float vm = fmaxf(g_prmax[((0*Bc + b)*Lc + i)*Pc + p],
                         g_prmax[((1*Bc + b)*Lc + i)*Pc + p]);
        float vs = g_prsum[((0*Bc + b)*Lc + i)*Pc + p] +
                   g_prsum[((1*Bc + b)*Lc + i)*Pc + p];
        orow[23 + p] = vm * (m1 * maxm2);
        orow[43 + p] = (m1 * vs) / fmaxf(m1 * cnt2, EPSF);
    }

    #pragma unroll
    for (int pr = 0; pr < 3; pr++) {
        const float* part = (pr == 0) ? lastv : ((pr == 1) ? &amn[il][0] : &amx[il][0]);
        float saa = 0.f, sab = 0.f, sbb = 0.f;
        if (q == 0) {
            #pragma unroll 4
            for (int h = 0; h < Hc; h++) {
                float a = v1t[il][h], bv = part[h];
                sab = fmaf(a, bv, sab);
                saa = fmaf(a, a, saa);
                sbb = fmaf(bv, bv, sbb);
            }
        } else {
            int p = q - 1;
            #pragma unroll 4
            for (int h = 0; h < Hc; h++) {
                float a = v1t[il][h], bv = part[h], w = wsq[pr][h][p];
                sab = fmaf(w, a*bv, sab);
                saa = fmaf(w, a*a, saa);
                sbb = fmaf(w, bv*bv, sbb);
            }
        }
        float val = sab / (fmaxf(sqrtf(saa), EPSF) * fmaxf(sqrtf(sbb), EPSF));
        int col = (pr == 0) ? ((q == 0) ? 2 : 3 + (q - 1))
                : (pr == 1) ? ((q == 0) ? 63 : 64 + (q - 1))
                :             ((q == 0) ? 84 : 85 + (q - 1));
        orow[col] = val;
    }
}

// ---------------- launch ----------------
extern "C" void kernel_launch(void* const* d_in, const int* in_sizes, int n_in,
                              void* d_out, int out_size) {
    const float* ctxp  = (const float*)d_in[0];
    const int*   maskp = (const int*)  d_in[1];
    const float* ctxh  = (const float*)d_in[2];
    const int*   maskh = (const int*)  d_in[3];
    const float* w0    = (const float*)d_in[4];
    const float* w1    = (const float*)d_in[5];
    const float* w2    = (const float*)d_in[6];
    const float* w3    = (const float*)d_in[7];
    float* out = (float*)d_out;

    const int SM0 = (Lc*HPAD + Hc*Pc + Lc) * 4;                  // ~60.5 KB
    const int SM1 = (Lc*HPAD + 3*Lc + 8*HPAD + Lc*9) * 4;
    cudaFuncSetAttribute(k0_prep, cudaFuncAttributeMaxDynamicSharedMemorySize, SM0);
    cudaFuncSetAttribute(k1_cos,  cudaFuncAttributeMaxDynamicSharedMemorySize, SM1);

    // order chosen so the ncu capture slot (4th launch) lands on k4_sym
    k0_prep<<<dim3(Bc, 2), 256, SM0>>>(ctxp, maskp, ctxh, maskh, w1);
    k1_cos<<<dim3(Bc, 16), 256, SM1>>>();
    k2_colstats<<<Bc, Lc>>>();
    k4_sym<<<dim3(Bc, Pc, 2), 256>>>(w1, out);
    k3_att<<<dim3(Bc, 16, 2), Lc>>>();
    k5_final<<<dim3(Bc, 2, 8), 336>>>(w0, w2, w3, out);
}